// round 2
// baseline (speedup 1.0000x reference)
#include <cuda_runtime.h>
#include <cuda_bf16.h>

// GGMLLinear: out[o] = sum_k x[k] * scales[o, k/32] * q[o,k] + bias[o]
// x: [1, 4096] f32, q: [14336, 4096] int32 (int8-range), scales: [14336, 128] f32,
// bias: [14336] f32, out: [1, 14336] f32.
//
// Memory-bound GEMV (235MB of q per call). R2: fine-grained 64-thread CTAs
// (2 rows each, grid=7168) to kill the end-of-kernel imbalance tail; no smem
// staging (x is L1-resident via __ldg, removes per-CTA startup bubble +
// barrier); __ldcs evict-first on the q stream to protect L2 residency of
// x/scales.

#define IN_DIM 4096
#define OUT_DIM 14336
#define NB (IN_DIM / 32)          // 128 scale blocks per row
#define ROWS_PER_CTA 2
#define THREADS 64

__global__ __launch_bounds__(THREADS)
void ggml_q8_gemv(const float* __restrict__ x,
                  const int* __restrict__ q,
                  const float* __restrict__ scales,
                  const float* __restrict__ bias,
                  float* __restrict__ out)
{
    const int warp = threadIdx.x >> 5;
    const int lane = threadIdx.x & 31;
    const int row  = blockIdx.x * ROWS_PER_CTA + warp;   // grid sized exactly

    const int4*   qrow = reinterpret_cast<const int4*>(q + (size_t)row * IN_DIM);
    const float*  srow = scales + (size_t)row * NB;
    const float4* x4   = reinterpret_cast<const float4*>(x);

    float acc = 0.0f;

    // 1024 int4 per row / 32 lanes = 32 steps. idx4 = step*32 + lane.
    // scale index: (idx4*4)/32 = idx4 >> 3 (a 16B group never crosses a 32-block).
    #pragma unroll 8
    for (int it = 0; it < 32; ++it) {
        const int idx4 = it * 32 + lane;
        const int4   qv = __ldcs(&qrow[idx4]);   // evict-first: pure stream
        const float4 xv = __ldg(&x4[idx4]);      // L1-resident (16KB total)
        const float  s  = __ldg(&srow[idx4 >> 3]);
        float dot = xv.x * (float)qv.x;
        dot = fmaf(xv.y, (float)qv.y, dot);
        dot = fmaf(xv.z, (float)qv.z, dot);
        dot = fmaf(xv.w, (float)qv.w, dot);
        acc = fmaf(s, dot, acc);
    }

    // Warp reduction
    #pragma unroll
    for (int off = 16; off > 0; off >>= 1)
        acc += __shfl_xor_sync(0xffffffffu, acc, off);

    if (lane == 0)
        out[row] = acc + __ldg(&bias[row]);
}

extern "C" void kernel_launch(void* const* d_in, const int* in_sizes, int n_in,
                              void* d_out, int out_size)
{
    const float* x      = (const float*)d_in[0];
    const int*   q      = (const int*)d_in[1];
    const float* scales = (const float*)d_in[2];
    const float* bias   = (const float*)d_in[3];
    float*       out    = (float*)d_out;

    const int grid = OUT_DIM / ROWS_PER_CTA;   // 7168
    ggml_q8_gemv<<<grid, THREADS>>>(x, q, scales, bias, out);
}